// round 1
// baseline (speedup 1.0000x reference)
#include <cuda_runtime.h>
#include <cmath>

#define DIMX 768
#define NHEAD 12
#define HD 64
#define BATCH 4
#define SEQ 2048
#define ROWS_TOT (BATCH*SEQ)   /* 8192 */
#define ATTN_SCALE 0.125f      /* 64^-0.5 */

// ---- scratch (allocation-free: __device__ globals) ----
__device__ float g_q[BATCH*NHEAD*SEQ*HD];
__device__ float g_k[BATCH*NHEAD*SEQ*HD];
__device__ float g_v[BATCH*NHEAD*SEQ*HD];
__device__ float g_att[ROWS_TOT*DIMX];

// ============================================================
// QKV GEMM:  C[m,j] = sum_k X[m,k] * W[j,k] + bias[j]
// BM=128, BN=64, BK=16, 256 threads, 8x4 per thread.
// Epilogue scatters into g_q / g_k / g_v in [B,H,N,Hd] layout.
// ============================================================
__global__ __launch_bounds__(256) void qkv_gemm(const float* __restrict__ X,
                                                const float* __restrict__ W,
                                                const float* __restrict__ bias)
{
    __shared__ float As[16][132];
    __shared__ float Bs[16][68];
    const int tid = threadIdx.x;
    const int tx = tid & 15, ty = tid >> 4;
    const int bm = blockIdx.y * 128;
    const int bn = blockIdx.x * 64;

    float acc[8][4] = {};

    for (int k0 = 0; k0 < DIMX; k0 += 16) {
        #pragma unroll
        for (int t = 0; t < 2; t++) {
            int lin = (tid + t*256) * 4;
            int m = lin >> 4, kk = lin & 15;
            float4 v4 = *(const float4*)&X[(size_t)(bm+m)*DIMX + k0 + kk];
            As[kk+0][m] = v4.x; As[kk+1][m] = v4.y;
            As[kk+2][m] = v4.z; As[kk+3][m] = v4.w;
        }
        {
            int lin = tid * 4;
            int n = lin >> 4, kk = lin & 15;
            float4 v4 = *(const float4*)&W[(size_t)(bn+n)*DIMX + k0 + kk];
            Bs[kk+0][n] = v4.x; Bs[kk+1][n] = v4.y;
            Bs[kk+2][n] = v4.z; Bs[kk+3][n] = v4.w;
        }
        __syncthreads();
        #pragma unroll
        for (int kk = 0; kk < 16; kk++) {
            float4 a0 = *(const float4*)&As[kk][ty*8];
            float4 a1 = *(const float4*)&As[kk][ty*8+4];
            float4 b0 = *(const float4*)&Bs[kk][tx*4];
            float a[8] = {a0.x,a0.y,a0.z,a0.w,a1.x,a1.y,a1.z,a1.w};
            float bb[4] = {b0.x,b0.y,b0.z,b0.w};
            #pragma unroll
            for (int i = 0; i < 8; i++)
                #pragma unroll
                for (int j = 0; j < 4; j++)
                    acc[i][j] = fmaf(a[i], bb[j], acc[i][j]);
        }
        __syncthreads();
    }

    // bn is a multiple of 64 -> whole block lands in one (c, h); d = col index
    const int c = bn / DIMX;             // 0=Q 1=K 2=V
    const int h = (bn % DIMX) / HD;
    float* dst = (c == 0) ? g_q : (c == 1) ? g_k : g_v;
    const float4 b4 = *(const float4*)&bias[bn + tx*4];
    #pragma unroll
    for (int i = 0; i < 8; i++) {
        int m  = bm + ty*8 + i;
        int b_ = m >> 11, n_ = m & 2047;
        float4 o = make_float4(acc[i][0] + b4.x, acc[i][1] + b4.y,
                               acc[i][2] + b4.z, acc[i][3] + b4.w);
        *(float4*)&dst[(((size_t)(b_*NHEAD + h))*SEQ + n_)*HD + tx*4] = o;
    }
}

// ============================================================
// Flash attention: one block = (b*h, 64 query rows).
// Online softmax over 32 KV tiles of 64. smem: Q/K/V/P [64][68].
// ============================================================
__global__ __launch_bounds__(256) void attn_kernel()
{
    extern __shared__ float sm[];
    float* Qs = sm;
    float* Ks = sm + 64*68;
    float* Vs = sm + 2*64*68;
    float* Ps = sm + 3*64*68;

    const int tid = threadIdx.x;
    const int tx = tid & 15, ty = tid >> 4;
    const int bh = blockIdx.y;
    const int q0 = blockIdx.x * 64;
    const size_t base = (size_t)bh * SEQ * HD;

    // load Q tile, pre-scaled
    #pragma unroll
    for (int t = 0; t < 4; t++) {
        int lin = (tid + t*256) * 4;
        int r = lin >> 6, d = lin & 63;
        float4 v4 = *(const float4*)&g_q[base + (size_t)(q0+r)*HD + d];
        v4.x *= ATTN_SCALE; v4.y *= ATTN_SCALE; v4.z *= ATTN_SCALE; v4.w *= ATTN_SCALE;
        *(float4*)&Qs[r*68 + d] = v4;
    }

    float m_i[4], l_i[4], acc[4][4];
    #pragma unroll
    for (int i = 0; i < 4; i++) {
        m_i[i] = -INFINITY; l_i[i] = 0.f;
        #pragma unroll
        for (int j = 0; j < 4; j++) acc[i][j] = 0.f;
    }

    for (int j0 = 0; j0 < SEQ; j0 += 64) {
        __syncthreads();   // prior P@V reads done before overwriting K/V
        #pragma unroll
        for (int t = 0; t < 4; t++) {
            int lin = (tid + t*256) * 4;
            int r = lin >> 6, d = lin & 63;
            *(float4*)&Ks[r*68 + d] = *(const float4*)&g_k[base + (size_t)(j0+r)*HD + d];
            *(float4*)&Vs[r*68 + d] = *(const float4*)&g_v[base + (size_t)(j0+r)*HD + d];
        }
        __syncthreads();

        // S = Q K^T (Q already scaled)
        float s[4][4] = {};
        #pragma unroll
        for (int d0 = 0; d0 < 64; d0 += 4) {
            float4 q4[4], k4[4];
            #pragma unroll
            for (int i = 0; i < 4; i++) q4[i] = *(const float4*)&Qs[(ty*4+i)*68 + d0];
            #pragma unroll
            for (int j = 0; j < 4; j++) k4[j] = *(const float4*)&Ks[(tx*4+j)*68 + d0];
            #pragma unroll
            for (int i = 0; i < 4; i++)
                #pragma unroll
                for (int j = 0; j < 4; j++) {
                    s[i][j] = fmaf(q4[i].x, k4[j].x, s[i][j]);
                    s[i][j] = fmaf(q4[i].y, k4[j].y, s[i][j]);
                    s[i][j] = fmaf(q4[i].z, k4[j].z, s[i][j]);
                    s[i][j] = fmaf(q4[i].w, k4[j].w, s[i][j]);
                }
        }

        // online softmax (row reductions within 16-lane groups)
        #pragma unroll
        for (int i = 0; i < 4; i++) {
            float rm = fmaxf(fmaxf(s[i][0], s[i][1]), fmaxf(s[i][2], s[i][3]));
            #pragma unroll
            for (int o = 1; o < 16; o <<= 1)
                rm = fmaxf(rm, __shfl_xor_sync(0xFFFFFFFFu, rm, o));
            float mn = fmaxf(m_i[i], rm);
            float alpha = __expf(m_i[i] - mn);
            float rs = 0.f;
            #pragma unroll
            for (int j = 0; j < 4; j++) {
                float p = __expf(s[i][j] - mn);
                s[i][j] = p; rs += p;
            }
            #pragma unroll
            for (int o = 1; o < 16; o <<= 1)
                rs += __shfl_xor_sync(0xFFFFFFFFu, rs, o);
            l_i[i] = l_i[i]*alpha + rs;
            m_i[i] = mn;
            #pragma unroll
            for (int j = 0; j < 4; j++) acc[i][j] *= alpha;
            *(float4*)&Ps[(ty*4+i)*68 + tx*4] =
                make_float4(s[i][0], s[i][1], s[i][2], s[i][3]);
        }
        __syncthreads();

        // O += P @ V
        #pragma unroll 4
        for (int kv = 0; kv < 64; kv++) {
            float4 vv = *(const float4*)&Vs[kv*68 + tx*4];
            #pragma unroll
            for (int i = 0; i < 4; i++) {
                float p = Ps[(ty*4+i)*68 + kv];
                acc[i][0] = fmaf(p, vv.x, acc[i][0]);
                acc[i][1] = fmaf(p, vv.y, acc[i][1]);
                acc[i][2] = fmaf(p, vv.z, acc[i][2]);
                acc[i][3] = fmaf(p, vv.w, acc[i][3]);
            }
        }
    }

    const int b_ = bh / NHEAD, h = bh % NHEAD;
    #pragma unroll
    for (int i = 0; i < 4; i++) {
        float inv = 1.0f / l_i[i];
        int row = q0 + ty*4 + i;
        float4 o = make_float4(acc[i][0]*inv, acc[i][1]*inv,
                               acc[i][2]*inv, acc[i][3]*inv);
        *(float4*)&g_att[((size_t)(b_*SEQ + row))*DIMX + h*HD + tx*4] = o;
    }
}

// ============================================================
// Proj GEMM: out[m,j] = sum_k att[m,k] * W[j,k] + bias[j]
// ============================================================
__global__ __launch_bounds__(256) void proj_gemm(const float* __restrict__ W,
                                                 const float* __restrict__ bias,
                                                 float* __restrict__ out)
{
    __shared__ float As[16][132];
    __shared__ float Bs[16][68];
    const int tid = threadIdx.x;
    const int tx = tid & 15, ty = tid >> 4;
    const int bm = blockIdx.y * 128;
    const int bn = blockIdx.x * 64;

    float acc[8][4] = {};

    for (int k0 = 0; k0 < DIMX; k0 += 16) {
        #pragma unroll
        for (int t = 0; t < 2; t++) {
            int lin = (tid + t*256) * 4;
            int m = lin >> 4, kk = lin & 15;
            float4 v4 = *(const float4*)&g_att[(size_t)(bm+m)*DIMX + k0 + kk];
            As[kk+0][m] = v4.x; As[kk+1][m] = v4.y;
            As[kk+2][m] = v4.z; As[kk+3][m] = v4.w;
        }
        {
            int lin = tid * 4;
            int n = lin >> 4, kk = lin & 15;
            float4 v4 = *(const float4*)&W[(size_t)(bn+n)*DIMX + k0 + kk];
            Bs[kk+0][n] = v4.x; Bs[kk+1][n] = v4.y;
            Bs[kk+2][n] = v4.z; Bs[kk+3][n] = v4.w;
        }
        __syncthreads();
        #pragma unroll
        for (int kk = 0; kk < 16; kk++) {
            float4 a0 = *(const float4*)&As[kk][ty*8];
            float4 a1 = *(const float4*)&As[kk][ty*8+4];
            float4 b0 = *(const float4*)&Bs[kk][tx*4];
            float a[8] = {a0.x,a0.y,a0.z,a0.w,a1.x,a1.y,a1.z,a1.w};
            float bb[4] = {b0.x,b0.y,b0.z,b0.w};
            #pragma unroll
            for (int i = 0; i < 8; i++)
                #pragma unroll
                for (int j = 0; j < 4; j++)
                    acc[i][j] = fmaf(a[i], bb[j], acc[i][j]);
        }
        __syncthreads();
    }

    const float4 b4 = *(const float4*)&bias[bn + tx*4];
    #pragma unroll
    for (int i = 0; i < 8; i++) {
        int m = bm + ty*8 + i;
        float4 o = make_float4(acc[i][0] + b4.x, acc[i][1] + b4.y,
                               acc[i][2] + b4.z, acc[i][3] + b4.w);
        *(float4*)&out[(size_t)m*DIMX + bn + tx*4] = o;
    }
}

// ============================================================
extern "C" void kernel_launch(void* const* d_in, const int* in_sizes, int n_in,
                              void* d_out, int out_size)
{
    const float* x      = (const float*)d_in[0];
    const float* qkv_w  = (const float*)d_in[1];
    const float* qkv_b  = (const float*)d_in[2];
    const float* proj_w = (const float*)d_in[3];
    const float* proj_b = (const float*)d_in[4];
    float* out = (float*)d_out;

    (void)in_sizes; (void)n_in; (void)out_size;

    // attention needs 4 * 64*68*4 = 69632 B dynamic smem (> 48KB default)
    cudaFuncSetAttribute(attn_kernel,
                         cudaFuncAttributeMaxDynamicSharedMemorySize, 69632);

    dim3 g1(2304/64, ROWS_TOT/128);   // (36, 64)
    qkv_gemm<<<g1, 256>>>(x, qkv_w, qkv_b);

    dim3 g2(SEQ/64, BATCH*NHEAD);     // (32, 48)
    attn_kernel<<<g2, 256, 69632>>>();

    dim3 g3(DIMX/64, ROWS_TOT/128);   // (12, 64)
    proj_gemm<<<g3, 256>>>(proj_w, proj_b, out);
}

// round 2
// speedup vs baseline: 2.3745x; 2.3745x over previous
#include <cuda_runtime.h>
#include <cuda_bf16.h>
#include <cmath>

#define DIMX 768
#define NHEAD 12
#define HD 64
#define BATCH 4
#define SEQ 2048
#define ROWS_TOT (BATCH*SEQ)   /* 8192 */
#define ATTN_SCALE 0.125f

// ---- scratch (allocation-free: __device__ globals) ----
__device__ float g_q[BATCH*NHEAD*SEQ*HD];
__device__ float g_k[BATCH*NHEAD*SEQ*HD];
__device__ float g_v[BATCH*NHEAD*SEQ*HD];
__device__ float g_att[ROWS_TOT*DIMX];

// ---- mma.sync m16n8k16 bf16 (row.col), fp32 accum ----
#define MMA16816(d0,d1,d2,d3,a0,a1,a2,a3,b0,b1)                              \
  asm volatile("mma.sync.aligned.m16n8k16.row.col.f32.bf16.bf16.f32 "        \
               "{%0,%1,%2,%3}, {%4,%5,%6,%7}, {%8,%9}, {%0,%1,%2,%3};\n"     \
               : "+f"(d0), "+f"(d1), "+f"(d2), "+f"(d3)                      \
               : "r"(a0), "r"(a1), "r"(a2), "r"(a3), "r"(b0), "r"(b1))

// split two fp32 into packed bf16x2 (hi) and residual bf16x2 (lo) registers
__device__ __forceinline__ void split2(float x, float y, unsigned &h, unsigned &l)
{
    __nv_bfloat162 hb = __floats2bfloat162_rn(x, y);
    float rx = x - __bfloat162float(hb.x);
    float ry = y - __bfloat162float(hb.y);
    __nv_bfloat162 lb = __floats2bfloat162_rn(rx, ry);
    h = *reinterpret_cast<unsigned*>(&hb);
    l = *reinterpret_cast<unsigned*>(&lb);
}

// split two fp32 and store packed pairs directly to smem
__device__ __forceinline__ void split_store(float x, float y,
                                            __nv_bfloat16* ph, __nv_bfloat16* pl)
{
    __nv_bfloat162 hb = __floats2bfloat162_rn(x, y);
    *reinterpret_cast<__nv_bfloat162*>(ph) = hb;
    float rx = x - __bfloat162float(hb.x);
    float ry = y - __bfloat162float(hb.y);
    *reinterpret_cast<__nv_bfloat162*>(pl) = __floats2bfloat162_rn(rx, ry);
}

__device__ __forceinline__ void split1(float x, __nv_bfloat16 &h, __nv_bfloat16 &l)
{
    h = __float2bfloat16(x);
    l = __float2bfloat16(x - __bfloat162float(h));
}

// ============================================================
// bf16x3 GEMM:  C[m,j] = sum_k A[m,k] * W[j,k] + bias[j]
// BM=128 BN=128 BK=32, 256 threads, warp grid 2(m) x 4(n),
// warp tile 64x32, m16n8k16 frags. QKV=true scatters to g_q/g_k/g_v.
// ============================================================
template<bool QKV>
__global__ __launch_bounds__(256) void gemm_bf16x3(const float* __restrict__ Ain,
                                                   const float* __restrict__ W,
                                                   const float* __restrict__ bias,
                                                   float* __restrict__ out)
{
    __shared__ __align__(16) __nv_bfloat16 Ah[128][40], Al[128][40];
    __shared__ __align__(16) __nv_bfloat16 Bh[128][40], Bl[128][40];

    const float* __restrict__ A = QKV ? Ain : (const float*)g_att;

    const int tid  = threadIdx.x;
    const int lane = tid & 31;
    const int w    = tid >> 5;
    const int g    = lane >> 2;      // 0..7
    const int tig  = lane & 3;       // 0..3
    const int wm   = w & 1;          // 2 warp rows
    const int wn   = w >> 1;         // 4 warp cols
    const int bm   = blockIdx.y * 128;
    const int bn   = blockIdx.x * 128;

    float acc[4][4][4];
    #pragma unroll
    for (int i = 0; i < 4; i++)
        #pragma unroll
        for (int j = 0; j < 4; j++)
            #pragma unroll
            for (int r = 0; r < 4; r++) acc[i][j][r] = 0.f;

    for (int k0 = 0; k0 < DIMX; k0 += 32) {
        #pragma unroll
        for (int t = 0; t < 4; t++) {
            int idx = tid + t*256;
            int m  = idx >> 3;
            int kq = (idx & 7) * 4;
            float4 va = *(const float4*)&A[(size_t)(bm+m)*DIMX + k0 + kq];
            split_store(va.x, va.y, &Ah[m][kq],   &Al[m][kq]);
            split_store(va.z, va.w, &Ah[m][kq+2], &Al[m][kq+2]);
            float4 vb = *(const float4*)&W[(size_t)(bn+m)*DIMX + k0 + kq];
            split_store(vb.x, vb.y, &Bh[m][kq],   &Bl[m][kq]);
            split_store(vb.z, vb.w, &Bh[m][kq+2], &Bl[m][kq+2]);
        }
        __syncthreads();

        #pragma unroll
        for (int ks = 0; ks < 32; ks += 16) {
            const int kb = ks + tig*2;
            unsigned ah[4][4], al[4][4];
            #pragma unroll
            for (int mf = 0; mf < 4; mf++) {
                int rm = wm*64 + mf*16 + g;
                ah[mf][0] = *(const unsigned*)&Ah[rm  ][kb  ];
                ah[mf][1] = *(const unsigned*)&Ah[rm+8][kb  ];
                ah[mf][2] = *(const unsigned*)&Ah[rm  ][kb+8];
                ah[mf][3] = *(const unsigned*)&Ah[rm+8][kb+8];
                al[mf][0] = *(const unsigned*)&Al[rm  ][kb  ];
                al[mf][1] = *(const unsigned*)&Al[rm+8][kb  ];
                al[mf][2] = *(const unsigned*)&Al[rm  ][kb+8];
                al[mf][3] = *(const unsigned*)&Al[rm+8][kb+8];
            }
            #pragma unroll
            for (int nf = 0; nf < 4; nf++) {
                int n = wn*32 + nf*8 + g;
                unsigned bh0 = *(const unsigned*)&Bh[n][kb  ];
                unsigned bh1 = *(const unsigned*)&Bh[n][kb+8];
                unsigned bl0 = *(const unsigned*)&Bl[n][kb  ];
                unsigned bl1 = *(const unsigned*)&Bl[n][kb+8];
                #pragma unroll
                for (int mf = 0; mf < 4; mf++) {
                    MMA16816(acc[mf][nf][0], acc[mf][nf][1], acc[mf][nf][2], acc[mf][nf][3],
                             ah[mf][0], ah[mf][1], ah[mf][2], ah[mf][3], bh0, bh1);
                    MMA16816(acc[mf][nf][0], acc[mf][nf][1], acc[mf][nf][2], acc[mf][nf][3],
                             ah[mf][0], ah[mf][1], ah[mf][2], ah[mf][3], bl0, bl1);
                    MMA16816(acc[mf][nf][0], acc[mf][nf][1], acc[mf][nf][2], acc[mf][nf][3],
                             al[mf][0], al[mf][1], al[mf][2], al[mf][3], bh0, bh1);
                }
            }
        }
        __syncthreads();
    }

    // epilogue
    #pragma unroll
    for (int nf = 0; nf < 4; nf++) {
        int col = bn + wn*32 + nf*8 + tig*2;
        float bx = bias[col], by = bias[col+1];
        if (QKV) {
            int c  = col / DIMX;            // 0=Q 1=K 2=V
            int hh = (col % DIMX) >> 6;
            int dd = col & 63;
            float* dst = (c == 0) ? g_q : (c == 1) ? g_k : g_v;
            #pragma unroll
            for (int mf = 0; mf < 4; mf++)
                #pragma unroll
                for (int h2 = 0; h2 < 2; h2++) {
                    int row = bm + wm*64 + mf*16 + g + h2*8;
                    int b_ = row >> 11, n_ = row & 2047;
                    float2 v = make_float2(acc[mf][nf][h2*2+0] + bx,
                                           acc[mf][nf][h2*2+1] + by);
                    *(float2*)&dst[(((size_t)(b_*NHEAD + hh))*SEQ + n_)*HD + dd] = v;
                }
        } else {
            #pragma unroll
            for (int mf = 0; mf < 4; mf++)
                #pragma unroll
                for (int h2 = 0; h2 < 2; h2++) {
                    int row = bm + wm*64 + mf*16 + g + h2*8;
                    float2 v = make_float2(acc[mf][nf][h2*2+0] + bx,
                                           acc[mf][nf][h2*2+1] + by);
                    *(float2*)&out[(size_t)row*DIMX + col] = v;
                }
        }
    }
}

// ============================================================
// Flash attention, bf16x3 tensor-core version.
// Block = (b*h, 128 query rows), 8 warps (16 rows each).
// S and P live entirely in registers (C-frag == A-frag layout).
// ============================================================
__global__ __launch_bounds__(256) void attn_mma()
{
    __shared__ __align__(16) __nv_bfloat16 Khi[64][72],  Klo[64][72];
    __shared__ __align__(16) __nv_bfloat16 Vthi[64][66], Vtlo[64][66];

    const int tid  = threadIdx.x;
    const int lane = tid & 31;
    const int w    = tid >> 5;
    const int g    = lane >> 2;
    const int tig  = lane & 3;
    const int bh   = blockIdx.y;
    const int q0   = blockIdx.x * 128;
    const size_t base = (size_t)bh * SEQ * HD;
    const int row0 = q0 + w*16 + g;      // this thread's rows: row0, row0+8

    // Q fragments resident in registers (scaled, split hi/lo)
    unsigned qhi[4][4], qlo[4][4];
    #pragma unroll
    for (int ks = 0; ks < 4; ks++) {
        int c0 = ks*16 + tig*2;
        float2 v;
        v = *(const float2*)&g_q[base + (size_t)row0*HD + c0];
        split2(v.x*ATTN_SCALE, v.y*ATTN_SCALE, qhi[ks][0], qlo[ks][0]);
        v = *(const float2*)&g_q[base + (size_t)(row0+8)*HD + c0];
        split2(v.x*ATTN_SCALE, v.y*ATTN_SCALE, qhi[ks][1], qlo[ks][1]);
        v = *(const float2*)&g_q[base + (size_t)row0*HD + c0 + 8];
        split2(v.x*ATTN_SCALE, v.y*ATTN_SCALE, qhi[ks][2], qlo[ks][2]);
        v = *(const float2*)&g_q[base + (size_t)(row0+8)*HD + c0 + 8];
        split2(v.x*ATTN_SCALE, v.y*ATTN_SCALE, qhi[ks][3], qlo[ks][3]);
    }

    float m0 = -INFINITY, m1 = -INFINITY, l0 = 0.f, l1 = 0.f;
    float o[8][4];
    #pragma unroll
    for (int nf = 0; nf < 8; nf++)
        #pragma unroll
        for (int r = 0; r < 4; r++) o[nf][r] = 0.f;

    for (int j0 = 0; j0 < SEQ; j0 += 64) {
        __syncthreads();   // previous PV reads done before overwrite
        #pragma unroll
        for (int t = 0; t < 4; t++) {
            int idx = tid + t*256;
            int kv = idx >> 4;
            int dq = (idx & 15) * 4;
            float4 kk = *(const float4*)&g_k[base + (size_t)(j0+kv)*HD + dq];
            split_store(kk.x, kk.y, &Khi[kv][dq],   &Klo[kv][dq]);
            split_store(kk.z, kk.w, &Khi[kv][dq+2], &Klo[kv][dq+2]);
            float4 vv = *(const float4*)&g_v[base + (size_t)(j0+kv)*HD + dq];
            split1(vv.x, Vthi[dq+0][kv], Vtlo[dq+0][kv]);
            split1(vv.y, Vthi[dq+1][kv], Vtlo[dq+1][kv]);
            split1(vv.z, Vthi[dq+2][kv], Vtlo[dq+2][kv]);
            split1(vv.w, Vthi[dq+3][kv], Vtlo[dq+3][kv]);
        }
        __syncthreads();

        // ---- S = Q K^T ----
        float s[8][4];
        #pragma unroll
        for (int nf = 0; nf < 8; nf++)
            #pragma unroll
            for (int r = 0; r < 4; r++) s[nf][r] = 0.f;

        #pragma unroll
        for (int ks = 0; ks < 4; ks++) {
            int kb = ks*16 + tig*2;
            #pragma unroll
            for (int nf = 0; nf < 8; nf++) {
                int n = nf*8 + g;
                unsigned bh0 = *(const unsigned*)&Khi[n][kb  ];
                unsigned bh1 = *(const unsigned*)&Khi[n][kb+8];
                unsigned bl0 = *(const unsigned*)&Klo[n][kb  ];
                unsigned bl1 = *(const unsigned*)&Klo[n][kb+8];
                MMA16816(s[nf][0], s[nf][1], s[nf][2], s[nf][3],
                         qhi[ks][0], qhi[ks][1], qhi[ks][2], qhi[ks][3], bh0, bh1);
                MMA16816(s[nf][0], s[nf][1], s[nf][2], s[nf][3],
                         qhi[ks][0], qhi[ks][1], qhi[ks][2], qhi[ks][3], bl0, bl1);
                MMA16816(s[nf][0], s[nf][1], s[nf][2], s[nf][3],
                         qlo[ks][0], qlo[ks][1], qlo[ks][2], qlo[ks][3], bh0, bh1);
            }
        }

        // ---- online softmax (rows row0 and row0+8) ----
        float rm0 = -INFINITY, rm1 = -INFINITY;
        #pragma unroll
        for (int nf = 0; nf < 8; nf++) {
            rm0 = fmaxf(rm0, fmaxf(s[nf][0], s[nf][1]));
            rm1 = fmaxf(rm1, fmaxf(s[nf][2], s[nf][3]));
        }
        rm0 = fmaxf(rm0, __shfl_xor_sync(0xFFFFFFFFu, rm0, 1));
        rm0 = fmaxf(rm0, __shfl_xor_sync(0xFFFFFFFFu, rm0, 2));
        rm1 = fmaxf(rm1, __shfl_xor_sync(0xFFFFFFFFu, rm1, 1));
        rm1 = fmaxf(rm1, __shfl_xor_sync(0xFFFFFFFFu, rm1, 2));
        float mn0 = fmaxf(m0, rm0), mn1 = fmaxf(m1, rm1);
        float al0 = __expf(m0 - mn0), al1 = __expf(m1 - mn1);
        m0 = mn0; m1 = mn1;

        float rs0 = 0.f, rs1 = 0.f;
        #pragma unroll
        for (int nf = 0; nf < 8; nf++) {
            s[nf][0] = __expf(s[nf][0] - mn0);
            s[nf][1] = __expf(s[nf][1] - mn0);
            s[nf][2] = __expf(s[nf][2] - mn1);
            s[nf][3] = __expf(s[nf][3] - mn1);
            rs0 += s[nf][0] + s[nf][1];
            rs1 += s[nf][2] + s[nf][3];
        }
        rs0 += __shfl_xor_sync(0xFFFFFFFFu, rs0, 1);
        rs0 += __shfl_xor_sync(0xFFFFFFFFu, rs0, 2);
        rs1 += __shfl_xor_sync(0xFFFFFFFFu, rs1, 1);
        rs1 += __shfl_xor_sync(0xFFFFFFFFu, rs1, 2);
        l0 = l0*al0 + rs0;
        l1 = l1*al1 + rs1;

        #pragma unroll
        for (int nf = 0; nf < 8; nf++) {
            o[nf][0] *= al0; o[nf][1] *= al0;
            o[nf][2] *= al1; o[nf][3] *= al1;
        }

        // ---- O += P @ V  (P straight from regs: C-frag -> A-frag) ----
        #pragma unroll
        for (int jj = 0; jj < 4; jj++) {
            unsigned pah[4], pal[4];
            split2(s[2*jj  ][0], s[2*jj  ][1], pah[0], pal[0]);
            split2(s[2*jj  ][2], s[2*jj  ][3], pah[1], pal[1]);
            split2(s[2*jj+1][0], s[2*jj+1][1], pah[2], pal[2]);
            split2(s[2*jj+1][2], s[2*jj+1][3], pah[3], pal[3]);
            int kc = jj*16 + tig*2;
            #pragma unroll
            for (int nf = 0; nf < 8; nf++) {
                int d = nf*8 + g;
                unsigned vh0 = *(const unsigned*)&Vthi[d][kc  ];
                unsigned vh1 = *(const unsigned*)&Vthi[d][kc+8];
                unsigned vl0 = *(const unsigned*)&Vtlo[d][kc  ];
                unsigned vl1 = *(const unsigned*)&Vtlo[d][kc+8];
                MMA16816(o[nf][0], o[nf][1], o[nf][2], o[nf][3],
                         pah[0], pah[1], pah[2], pah[3], vh0, vh1);
                MMA16816(o[nf][0], o[nf][1], o[nf][2], o[nf][3],
                         pah[0], pah[1], pah[2], pah[3], vl0, vl1);
                MMA16816(o[nf][0], o[nf][1], o[nf][2], o[nf][3],
                         pal[0], pal[1], pal[2], pal[3], vh0, vh1);
            }
        }
    }

    // ---- epilogue: normalize and write [B,N,D] ----
    float inv0 = 1.0f / l0, inv1 = 1.0f / l1;
    int b_ = bh / NHEAD, hh = bh % NHEAD;
    #pragma unroll
    for (int nf = 0; nf < 8; nf++) {
        int col = hh*64 + nf*8 + tig*2;
        *(float2*)&g_att[((size_t)(b_*SEQ + row0  ))*DIMX + col] =
            make_float2(o[nf][0]*inv0, o[nf][1]*inv0);
        *(float2*)&g_att[((size_t)(b_*SEQ + row0+8))*DIMX + col] =
            make_float2(o[nf][2]*inv1, o[nf][3]*inv1);
    }
}

// ============================================================
extern "C" void kernel_launch(void* const* d_in, const int* in_sizes, int n_in,
                              void* d_out, int out_size)
{
    const float* x      = (const float*)d_in[0];
    const float* qkv_w  = (const float*)d_in[1];
    const float* qkv_b  = (const float*)d_in[2];
    const float* proj_w = (const float*)d_in[3];
    const float* proj_b = (const float*)d_in[4];
    float* out = (float*)d_out;
    (void)in_sizes; (void)n_in; (void)out_size;

    dim3 g1(2304/128, ROWS_TOT/128);   // (18, 64)
    gemm_bf16x3<true><<<g1, 256>>>(x, qkv_w, qkv_b, nullptr);

    dim3 g2(SEQ/128, BATCH*NHEAD);     // (16, 48)
    attn_mma<<<g2, 256>>>();

    dim3 g3(DIMX/128, ROWS_TOT/128);   // (6, 64)
    gemm_bf16x3<false><<<g3, 256>>>(nullptr, proj_w, proj_b, out);
}

// round 4
// speedup vs baseline: 3.6326x; 1.5299x over previous
#include <cuda_runtime.h>
#include <cuda_bf16.h>
#include <cstdint>
#include <cmath>

#define DIMX 768
#define NHEAD 12
#define HD 64
#define BATCH 4
#define SEQ 2048
#define ROWS_TOT (BATCH*SEQ)   /* 8192 */
#define ATTN_SCALE 0.125f      /* exact power of 2 */
#define BHT (BATCH*NHEAD)

// ---- scratch (allocation-free: __device__ globals) ----
// Q/K: [b,h,n,d] bf16 hi/lo.  V: transposed [b,h,d,n] bf16 hi/lo.
__device__ __nv_bfloat16 g_qhi[BHT*SEQ*HD], g_qlo[BHT*SEQ*HD];
__device__ __nv_bfloat16 g_khi[BHT*SEQ*HD], g_klo[BHT*SEQ*HD];
__device__ __nv_bfloat16 g_vthi[BHT*HD*SEQ], g_vtlo[BHT*HD*SEQ];
__device__ float g_att[ROWS_TOT*DIMX];

// ---- mma.sync m16n8k16 bf16 (row.col), fp32 accum ----
#define MMA16816(d0,d1,d2,d3,a0,a1,a2,a3,b0,b1)                              \
  asm volatile("mma.sync.aligned.m16n8k16.row.col.f32.bf16.bf16.f32 "        \
               "{%0,%1,%2,%3}, {%4,%5,%6,%7}, {%8,%9}, {%0,%1,%2,%3};\n"     \
               : "+f"(d0), "+f"(d1), "+f"(d2), "+f"(d3)                      \
               : "r"(a0), "r"(a1), "r"(a2), "r"(a3), "r"(b0), "r"(b1))

#define CP16(d, s)                                                            \
  asm volatile("cp.async.cg.shared.global [%0], [%1], 16;\n"                  \
               :: "r"(d), "l"(s))
#define CPCOMMIT asm volatile("cp.async.commit_group;\n")

__device__ __forceinline__ void split2(float x, float y,
                                       unsigned int &h, unsigned int &l)
{
    __nv_bfloat162 hb = __floats2bfloat162_rn(x, y);
    float rx = x - __bfloat162float(hb.x);
    float ry = y - __bfloat162float(hb.y);
    __nv_bfloat162 lb = __floats2bfloat162_rn(rx, ry);
    h = *reinterpret_cast<unsigned int*>(&hb);
    l = *reinterpret_cast<unsigned int*>(&lb);
}

__device__ __forceinline__ void split_store(float x, float y,
                                            __nv_bfloat16* ph, __nv_bfloat16* pl)
{
    __nv_bfloat162 hb = __floats2bfloat162_rn(x, y);
    *reinterpret_cast<__nv_bfloat162*>(ph) = hb;
    float rx = x - __bfloat162float(hb.x);
    float ry = y - __bfloat162float(hb.y);
    *reinterpret_cast<__nv_bfloat162*>(pl) = __floats2bfloat162_rn(rx, ry);
}

__device__ __forceinline__ void split1(float x, __nv_bfloat16 &h, __nv_bfloat16 &l)
{
    h = __float2bfloat16(x);
    l = __float2bfloat16(x - __bfloat162float(h));
}

// ============================================================
// bf16x3 GEMM, double-buffered smem + register prefetch.
// BM=128 BN=128 BK=32, 256 thr, warp grid 2(m)x4(n), 64x32/warp.
// QKV=true: epilogue scatters split bf16 Q(pre-scaled)/K/V(transposed).
// ============================================================
template<bool QKV>
__global__ __launch_bounds__(256) void gemm_bf16x3(const float* __restrict__ Ain,
                                                   const float* __restrict__ W,
                                                   const float* __restrict__ bias,
                                                   float* __restrict__ out)
{
    extern __shared__ __nv_bfloat16 smg[];
    const int AS = 128*40;                 // one array, elems
    // stage layout: [stage][Ah|Al|Bh|Bl][128][40]

    const float* __restrict__ A = QKV ? Ain : (const float*)g_att;

    const int tid  = threadIdx.x;
    const int lane = tid & 31;
    const int w    = tid >> 5;
    const int g    = lane >> 2;
    const int tig  = lane & 3;
    const int wm   = w & 1;
    const int wn   = w >> 1;
    const int bm   = blockIdx.y * 128;
    const int bn   = blockIdx.x * 128;

    float acc[4][4][4];
    #pragma unroll
    for (int i = 0; i < 4; i++)
        #pragma unroll
        for (int j = 0; j < 4; j++)
            #pragma unroll
            for (int r = 0; r < 4; r++) acc[i][j][r] = 0.f;

    float4 ra[4], rb[4];
    #pragma unroll
    for (int t = 0; t < 4; t++) {
        int idx = tid + t*256;
        int m  = idx >> 3;
        int kq = (idx & 7) * 4;
        ra[t] = *(const float4*)&A[(size_t)(bm+m)*DIMX + kq];
        rb[t] = *(const float4*)&W[(size_t)(bn+m)*DIMX + kq];
    }

    int s = 0;
    for (int k0 = 0; k0 < DIMX; k0 += 32) {
        __nv_bfloat16* Ah = smg + s*4*AS;
        __nv_bfloat16* Al = Ah + AS;
        __nv_bfloat16* Bh = Ah + 2*AS;
        __nv_bfloat16* Bl = Ah + 3*AS;

        #pragma unroll
        for (int t = 0; t < 4; t++) {
            int idx = tid + t*256;
            int m  = idx >> 3;
            int kq = (idx & 7) * 4;
            split_store(ra[t].x, ra[t].y, &Ah[m*40+kq],   &Al[m*40+kq]);
            split_store(ra[t].z, ra[t].w, &Ah[m*40+kq+2], &Al[m*40+kq+2]);
            split_store(rb[t].x, rb[t].y, &Bh[m*40+kq],   &Bl[m*40+kq]);
            split_store(rb[t].z, rb[t].w, &Bh[m*40+kq+2], &Bl[m*40+kq+2]);
        }
        __syncthreads();

        if (k0 + 32 < DIMX) {
            #pragma unroll
            for (int t = 0; t < 4; t++) {
                int idx = tid + t*256;
                int m  = idx >> 3;
                int kq = (idx & 7) * 4;
                ra[t] = *(const float4*)&A[(size_t)(bm+m)*DIMX + k0+32 + kq];
                rb[t] = *(const float4*)&W[(size_t)(bn+m)*DIMX + k0+32 + kq];
            }
        }

        #pragma unroll
        for (int ks = 0; ks < 32; ks += 16) {
            const int kb = ks + tig*2;
            unsigned int ah[4][4], al[4][4];
            #pragma unroll
            for (int mf = 0; mf < 4; mf++) {
                int rm = wm*64 + mf*16 + g;
                ah[mf][0] = *(const unsigned int*)&Ah[ rm   *40 + kb  ];
                ah[mf][1] = *(const unsigned int*)&Ah[(rm+8)*40 + kb  ];
                ah[mf][2] = *(const unsigned int*)&Ah[ rm   *40 + kb+8];
                ah[mf][3] = *(const unsigned int*)&Ah[(rm+8)*40 + kb+8];
                al[mf][0] = *(const unsigned int*)&Al[ rm   *40 + kb  ];
                al[mf][1] = *(const unsigned int*)&Al[(rm+8)*40 + kb  ];
                al[mf][2] = *(const unsigned int*)&Al[ rm   *40 + kb+8];
                al[mf][3] = *(const unsigned int*)&Al[(rm+8)*40 + kb+8];
            }
            #pragma unroll
            for (int nf = 0; nf < 4; nf++) {
                int n = wn*32 + nf*8 + g;
                unsigned int bh0 = *(const unsigned int*)&Bh[n*40 + kb  ];
                unsigned int bh1 = *(const unsigned int*)&Bh[n*40 + kb+8];
                unsigned int bl0 = *(const unsigned int*)&Bl[n*40 + kb  ];
                unsigned int bl1 = *(const unsigned int*)&Bl[n*40 + kb+8];
                #pragma unroll
                for (int mf = 0; mf < 4; mf++) {
                    MMA16816(acc[mf][nf][0], acc[mf][nf][1], acc[mf][nf][2], acc[mf][nf][3],
                             ah[mf][0], ah[mf][1], ah[mf][2], ah[mf][3], bh0, bh1);
                    MMA16816(acc[mf][nf][0], acc[mf][nf][1], acc[mf][nf][2], acc[mf][nf][3],
                             ah[mf][0], ah[mf][1], ah[mf][2], ah[mf][3], bl0, bl1);
                    MMA16816(acc[mf][nf][0], acc[mf][nf][1], acc[mf][nf][2], acc[mf][nf][3],
                             al[mf][0], al[mf][1], al[mf][2], al[mf][3], bh0, bh1);
                }
            }
        }
        s ^= 1;
    }

    // ---- epilogue ----
    #pragma unroll
    for (int nf = 0; nf < 4; nf++) {
        int col = bn + wn*32 + nf*8 + tig*2;
        float bx = bias[col], by = bias[col+1];
        if (QKV) {
            int c  = col / DIMX;            // 0=Q 1=K 2=V
            int hh = (col % DIMX) >> 6;
            int dd = col & 63;
            #pragma unroll
            for (int mf = 0; mf < 4; mf++)
                #pragma unroll
                for (int h2 = 0; h2 < 2; h2++) {
                    int row = bm + wm*64 + mf*16 + g + h2*8;
                    int b_ = row >> 11, n_ = row & 2047;
                    float vx = acc[mf][nf][h2*2+0] + bx;
                    float vy = acc[mf][nf][h2*2+1] + by;
                    if (c == 0) {
                        size_t idx = (((size_t)(b_*NHEAD + hh))*SEQ + n_)*HD + dd;
                        split_store(vx*ATTN_SCALE, vy*ATTN_SCALE, &g_qhi[idx], &g_qlo[idx]);
                    } else if (c == 1) {
                        size_t idx = (((size_t)(b_*NHEAD + hh))*SEQ + n_)*HD + dd;
                        split_store(vx, vy, &g_khi[idx], &g_klo[idx]);
                    } else {
                        size_t idx = (((size_t)(b_*NHEAD + hh))*HD + dd)*SEQ + n_;
                        split1(vx, g_vthi[idx],     g_vtlo[idx]);
                        split1(vy, g_vthi[idx+SEQ], g_vtlo[idx+SEQ]);
                    }
                }
        } else {
            #pragma unroll
            for (int mf = 0; mf < 4; mf++)
                #pragma unroll
                for (int h2 = 0; h2 < 2; h2++) {
                    int row = bm + wm*64 + mf*16 + g + h2*8;
                    float2 v = make_float2(acc[mf][nf][h2*2+0] + bx,
                                           acc[mf][nf][h2*2+1] + by);
                    *(float2*)&out[(size_t)row*DIMX + col] = v;
                }
        }
    }
}

// ============================================================
// Flash attention, bf16x3 + cp.async double-buffered K/V tiles.
// Block = (b*h, 128 query rows), 8 warps. S/P in registers.
// ============================================================
#define TSE (64*72)           /* elems per smem array  */
#define TSB (TSE*2)           /* bytes per smem array  */

__global__ __launch_bounds__(256) void attn_mma()
{
    extern __shared__ __nv_bfloat16 sma[];
    const unsigned int smem_u32 = (unsigned int)__cvta_generic_to_shared(sma);

    const int tid  = threadIdx.x;
    const int lane = tid & 31;
    const int w    = tid >> 5;
    const int g    = lane >> 2;
    const int tig  = lane & 3;
    const int bh   = blockIdx.y;
    const int q0   = blockIdx.x * 128;
    const size_t kbase = (size_t)bh * SEQ * HD;
    const size_t vbase = (size_t)bh * HD * SEQ;
    const int row0 = q0 + w*16 + g;

    // Q fragments (pre-scaled & pre-split in gmem)
    unsigned int qhi[4][4], qlo[4][4];
    #pragma unroll
    for (int ks = 0; ks < 4; ks++) {
        int c0 = ks*16 + tig*2;
        qhi[ks][0] = *(const unsigned int*)&g_qhi[kbase + (size_t) row0   *HD + c0];
        qhi[ks][1] = *(const unsigned int*)&g_qhi[kbase + (size_t)(row0+8)*HD + c0];
        qhi[ks][2] = *(const unsigned int*)&g_qhi[kbase + (size_t) row0   *HD + c0+8];
        qhi[ks][3] = *(const unsigned int*)&g_qhi[kbase + (size_t)(row0+8)*HD + c0+8];
        qlo[ks][0] = *(const unsigned int*)&g_qlo[kbase + (size_t) row0   *HD + c0];
        qlo[ks][1] = *(const unsigned int*)&g_qlo[kbase + (size_t)(row0+8)*HD + c0];
        qlo[ks][2] = *(const unsigned int*)&g_qlo[kbase + (size_t) row0   *HD + c0+8];
        qlo[ks][3] = *(const unsigned int*)&g_qlo[kbase + (size_t)(row0+8)*HD + c0+8];
    }

    float m0 = -INFINITY, m1 = -INFINITY, l0 = 0.f, l1 = 0.f;
    float o[8][4];
    #pragma unroll
    for (int nf = 0; nf < 8; nf++)
        #pragma unroll
        for (int r = 0; r < 4; r++) o[nf][r] = 0.f;

    auto load_tile = [&](int st, int j0) {
        unsigned int sb = smem_u32 + st*(4*TSB);
        #pragma unroll
        for (int t = 0; t < 2; t++) {
            int idx = tid*2 + t;          // 0..511
            int row = idx >> 3;
            int ch  = (idx & 7) * 8;      // bf16 elems (16B chunks)
            unsigned int doff = (unsigned int)(row*72 + ch) * 2;
            CP16(sb +         doff, &g_khi [kbase + (size_t)(j0+row)*HD + ch]);
            CP16(sb +   TSB + doff, &g_klo [kbase + (size_t)(j0+row)*HD + ch]);
            CP16(sb + 2*TSB + doff, &g_vthi[vbase + (size_t)row*SEQ + j0 + ch]);
            CP16(sb + 3*TSB + doff, &g_vtlo[vbase + (size_t)row*SEQ + j0 + ch]);
        }
    };

    load_tile(0, 0); CPCOMMIT;
    int s = 0;

    for (int j0 = 0; j0 < SEQ; j0 += 64) {
        if (j0 + 64 < SEQ) {
            load_tile(s^1, j0+64); CPCOMMIT;
            asm volatile("cp.async.wait_group 1;\n");
        } else {
            asm volatile("cp.async.wait_group 0;\n");
        }
        __syncthreads();

        const __nv_bfloat16* Kh = sma + s*4*TSE;
        const __nv_bfloat16* Kl = Kh + TSE;
        const __nv_bfloat16* Vh = Kh + 2*TSE;
        const __nv_bfloat16* Vl = Kh + 3*TSE;

        // ---- S = Q K^T ----
        float sres[8][4];
        #pragma unroll
        for (int nf = 0; nf < 8; nf++)
            #pragma unroll
            for (int r = 0; r < 4; r++) sres[nf][r] = 0.f;

        #pragma unroll
        for (int ks = 0; ks < 4; ks++) {
            int kb = ks*16 + tig*2;
            #pragma unroll
            for (int nf = 0; nf < 8; nf++) {
                int n = nf*8 + g;
                unsigned int b0h = *(const unsigned int*)&Kh[n*72 + kb  ];
                unsigned int b1h = *(const unsigned int*)&Kh[n*72 + kb+8];
                unsigned int b0l = *(const unsigned int*)&Kl[n*72 + kb  ];
                unsigned int b1l = *(const unsigned int*)&Kl[n*72 + kb+8];
                MMA16816(sres[nf][0], sres[nf][1], sres[nf][2], sres[nf][3],
                         qhi[ks][0], qhi[ks][1], qhi[ks][2], qhi[ks][3], b0h, b1h);
                MMA16816(sres[nf][0], sres[nf][1], sres[nf][2], sres[nf][3],
                         qhi[ks][0], qhi[ks][1], qhi[ks][2], qhi[ks][3], b0l, b1l);
                MMA16816(sres[nf][0], sres[nf][1], sres[nf][2], sres[nf][3],
                         qlo[ks][0], qlo[ks][1], qlo[ks][2], qlo[ks][3], b0h, b1h);
            }
        }

        // ---- online softmax ----
        float rm0 = -INFINITY, rm1 = -INFINITY;
        #pragma unroll
        for (int nf = 0; nf < 8; nf++) {
            rm0 = fmaxf(rm0, fmaxf(sres[nf][0], sres[nf][1]));
            rm1 = fmaxf(rm1, fmaxf(sres[nf][2], sres[nf][3]));
        }
        rm0 = fmaxf(rm0, __shfl_xor_sync(0xFFFFFFFFu, rm0, 1));
        rm0 = fmaxf(rm0, __shfl_xor_sync(0xFFFFFFFFu, rm0, 2));
        rm1 = fmaxf(rm1, __shfl_xor_sync(0xFFFFFFFFu, rm1, 1));
        rm1 = fmaxf(rm1, __shfl_xor_sync(0xFFFFFFFFu, rm1, 2));
        float mn0 = fmaxf(m0, rm0), mn1 = fmaxf(m1, rm1);
        float al0 = __expf(m0 - mn0), al1 = __expf(m1 - mn1);
        m0 = mn0; m1 = mn1;

        float rs0 = 0.f, rs1 = 0.f;
        #pragma unroll
        for (int nf = 0; nf < 8; nf++) {
            sres[nf][0] = __expf(sres[nf][0] - mn0);
            sres[nf][1] = __expf(sres[nf][1] - mn0);
            sres[nf][2] = __expf(sres[nf][2] - mn1);
            sres[nf][3] = __expf(sres[nf][3] - mn1);
            rs0 += sres[nf][0] + sres[nf][1];
            rs1 += sres[nf][2] + sres[nf][3];
        }
        rs0 += __shfl_xor_sync(0xFFFFFFFFu, rs0, 1);
        rs0 += __shfl_xor_sync(0xFFFFFFFFu, rs0, 2);
        rs1 += __shfl_xor_sync(0xFFFFFFFFu, rs1, 1);
        rs1 += __shfl_xor_sync(0xFFFFFFFFu, rs1, 2);
        l0 = l0*al0 + rs0;
        l1 = l1*al1 + rs1;

        #pragma unroll
        for (int nf = 0; nf < 8; nf++) {
            o[nf][0] *= al0; o[nf][1] *= al0;
            o[nf][2] *= al1; o[nf][3] *= al1;
        }

        // ---- O += P @ V ----
        #pragma unroll
        for (int jj = 0; jj < 4; jj++) {
            unsigned int pah[4], pal[4];
            split2(sres[2*jj  ][0], sres[2*jj  ][1], pah[0], pal[0]);
            split2(sres[2*jj  ][2], sres[2*jj  ][3], pah[1], pal[1]);
            split2(sres[2*jj+1][0], sres[2*jj+1][1], pah[2], pal[2]);
            split2(sres[2*jj+1][2], sres[2*jj+1][3], pah[3], pal[3]);
            int kc = jj*16 + tig*2;
            #pragma unroll
            for (int nf = 0; nf < 8; nf++) {
                int d = nf*8 + g;
                unsigned int v0h = *(const unsigned int*)&Vh[d*72 + kc  ];
                unsigned int v1h = *(const unsigned int*)&Vh[d*72 + kc+8];
                unsigned int v0l = *(const unsigned int*)&Vl[d*72 + kc  ];
                unsigned int v1l = *(const unsigned int*)&Vl[d*72 + kc+8];
                MMA16816(o[nf][0], o[nf][1], o[nf][2], o[nf][3],
                         pah[0], pah[1], pah[2], pah[3], v0h, v1h);
                MMA16816(o[nf][0], o[nf][1], o[nf][2], o[nf][3],
                         pah[0], pah[1], pah[2], pah[3], v0l, v1l);
                MMA16816(o[nf][0], o[nf][1], o[nf][2], o[nf][3],
                         pal[0], pal[1], pal[2], pal[3], v0h, v1h);
            }
        }

        s ^= 1;
        __syncthreads();   // compute done before next cp.async overwrite
    }

    // ---- epilogue ----
    float inv0 = 1.0f / l0, inv1 = 1.0f / l1;
    int b_ = bh / NHEAD, hh = bh % NHEAD;
    #pragma unroll
    for (int nf = 0; nf < 8; nf++) {
        int col = hh*64 + nf*8 + tig*2;
        *(float2*)&g_att[((size_t)(b_*SEQ + row0  ))*DIMX + col] =
            make_float2(o[nf][0]*inv0, o[nf][1]*inv0);
        *(float2*)&g_att[((size_t)(b_*SEQ + row0+8))*DIMX + col] =
            make_float2(o[nf][2]*inv1, o[nf][3]*inv1);
    }
}

// ============================================================
extern "C" void kernel_launch(void* const* d_in, const int* in_sizes, int n_in,
                              void* d_out, int out_size)
{
    const float* x      = (const float*)d_in[0];
    const float* qkv_w  = (const float*)d_in[1];
    const float* qkv_b  = (const float*)d_in[2];
    const float* proj_w = (const float*)d_in[3];
    const float* proj_b = (const float*)d_in[4];
    float* out = (float*)d_out;
    (void)in_sizes; (void)n_in; (void)out_size;

    const int gemm_smem = 2*4*128*40*2;        // 81920 B
    const int attn_smem = 2*4*TSB;             // 73728 B
    cudaFuncSetAttribute(gemm_bf16x3<true>,
                         cudaFuncAttributeMaxDynamicSharedMemorySize, gemm_smem);
    cudaFuncSetAttribute(gemm_bf16x3<false>,
                         cudaFuncAttributeMaxDynamicSharedMemorySize, gemm_smem);
    cudaFuncSetAttribute(attn_mma,
                         cudaFuncAttributeMaxDynamicSharedMemorySize, attn_smem);

    dim3 g1(2304/128, ROWS_TOT/128);   // (18, 64)
    gemm_bf16x3<true><<<g1, 256, gemm_smem>>>(x, qkv_w, qkv_b, nullptr);

    dim3 g2(SEQ/128, BATCH*NHEAD);     // (16, 48)
    attn_mma<<<g2, 256, attn_smem>>>();

    dim3 g3(DIMX/128, ROWS_TOT/128);   // (6, 64)
    gemm_bf16x3<false><<<g3, 256, gemm_smem>>>(nullptr, proj_w, proj_b, out);
}